// round 13
// baseline (speedup 1.0000x reference)
#include <cuda_runtime.h>
#include <cuda_bf16.h>
#include <cstdint>
#include <math.h>

// ---------------- problem constants ----------------
constexpr int Hdim   = 256;
constexpr int INdim  = 64;
constexpr int HD2    = 128;
constexpr int OUTdim = 12;
constexpr int NLAY   = 3;
constexpr int NGRAPH = 64;
constexpr int NMAX   = 50000;
constexpr int EMAX   = 600000;
constexpr int SCAN_B = 512;
constexpr int MAXBLK1 = (NMAX + SCAN_B - 1) / SCAN_B;

// weight scratch: bf16 split + transposed [N][K]
constexpr int NODE_OFF = 0;                      // 256 x 64
constexpr int CONV_OFF = 256 * 64;               // 3 x (256 x 256)
constexpr int WTOT     = CONV_OFF + 3 * 256 * 256;

// ---------------- scratch (device globals, no allocation) ----------------
__device__ float  g_bufA[(size_t)NMAX * Hdim];
__device__ float  g_bufB[(size_t)NMAX * Hdim];
__device__ float  g_dis[NMAX];
__device__ int    g_cnt[NMAX];
__device__ int    g_rowptr[NMAX + 1];
__device__ int    g_cursor[NMAX];
__device__ int    g_partial[NMAX];
__device__ int    g_bsum[MAXBLK1 + 1];
__device__ int2   g_csr[EMAX];
__device__ double g_stats[NLAY * 2 * Hdim];
__device__ float  g_scale[NLAY * Hdim];
__device__ float  g_shift[NLAY * Hdim];
__device__ float  g_pool[NGRAPH * Hdim];
__device__ int    g_ctr[8];
__device__ __nv_bfloat16 g_BtH[WTOT];
__device__ __nv_bfloat16 g_BtL[WTOT];
__device__ __nv_bfloat16 g_pAH[(size_t)NMAX * Hdim];
__device__ __nv_bfloat16 g_pAL[(size_t)NMAX * Hdim];
__device__ __nv_bfloat16 g_qAH[(size_t)NMAX * Hdim];
__device__ __nv_bfloat16 g_qAL[(size_t)NMAX * Hdim];

// ---------------- helpers ----------------
__device__ __forceinline__ uint32_t packbf2(float hi, float lo) {
    uint32_t d;
    asm("cvt.rn.bf16x2.f32 %0, %1, %2;" : "=r"(d) : "f"(hi), "f"(lo));
    return d;
}

__device__ __forceinline__ void split2(float x0, float x1, uint32_t& h, uint32_t& l) {
    h = packbf2(x1, x0);
    float f0 = __uint_as_float(h << 16);
    float f1 = __uint_as_float(h & 0xFFFF0000u);
    l = packbf2(x1 - f1, x0 - f0);
}

#define MMA_BF16(d, a, b)                                                       \
    asm volatile("mma.sync.aligned.m16n8k16.row.col.f32.bf16.bf16.f32 "        \
                 "{%0,%1,%2,%3},{%4,%5,%6,%7},{%8,%9},{%0,%1,%2,%3};"          \
                 : "+f"(d[0]), "+f"(d[1]), "+f"(d[2]), "+f"(d[3])              \
                 : "r"(a[0]), "r"(a[1]), "r"(a[2]), "r"(a[3]),                 \
                   "r"(b[0]), "r"(b[1]))

__device__ __forceinline__ void ldsm_x4(uint32_t& r0, uint32_t& r1,
                                        uint32_t& r2, uint32_t& r3, uint32_t addr) {
    asm volatile("ldmatrix.sync.aligned.m8n8.x4.shared.b16 {%0,%1,%2,%3}, [%4];"
                 : "=r"(r0), "=r"(r1), "=r"(r2), "=r"(r3) : "r"(addr));
}

__device__ __forceinline__ void cp16(uint32_t dst, const void* src, uint32_t sz) {
    asm volatile("cp.async.cg.shared.global [%0], [%1], 16, %2;"
                 :: "r"(dst), "l"(src), "r"(sz) : "memory");
}
__device__ __forceinline__ void cp8(uint32_t dst, const void* src) {
    asm volatile("cp.async.ca.shared.global [%0], [%1], 8;"
                 :: "r"(dst), "l"(src) : "memory");
}
#define CP_COMMIT() asm volatile("cp.async.commit_group;" ::: "memory")

// ---------------- prolog: zero + weight split + x split (one kernel) ----------
__global__ void prolog_k(const float* __restrict__ node_w, const float* __restrict__ conv_w,
                         const float4* __restrict__ x,
                         uint2* __restrict__ xH, uint2* __restrict__ xL,
                         int* __restrict__ cnt, double* __restrict__ stats,
                         float* __restrict__ pool, int* __restrict__ ctr, int N)
{
    int i = blockIdx.x * blockDim.x + threadIdx.x;
    if (i < N * 16) {                      // x split (N x 64 floats = N*16 float4)
        float4 v = x[i];
        uint32_t h0, l0, h1, l1;
        split2(v.x, v.y, h0, l0);
        split2(v.z, v.w, h1, l1);
        xH[i] = make_uint2(h0, h1);
        xL[i] = make_uint2(l0, l1);
    }
    if (i < WTOT) {                        // weight split + transpose
        float v;
        if (i < CONV_OFF) {
            int n = i / INdim, k = i % INdim;
            v = node_w[k * Hdim + n];
        } else {
            int rel = i - CONV_OFF;
            int l = rel >> 16;
            int r2 = rel & 65535;
            int n = r2 >> 8, k = r2 & 255;
            v = conv_w[l * 65536 + k * Hdim + n];
        }
        __nv_bfloat16 h = __float2bfloat16(v);
        __nv_bfloat16 lo = __float2bfloat16(v - __bfloat162float(h));
        g_BtH[i] = h;
        g_BtL[i] = lo;
    }
    if (i < N) cnt[i] = 0;
    if (i < NLAY * 2 * Hdim) stats[i] = 0.0;
    if (i < NGRAPH * Hdim) pool[i] = 0.0f;
    if (i < 8) ctr[i] = 0;
}

// ---------------- activation split (+ BN affine + relu) ----------------------
__global__ void asplit_k(const float4* __restrict__ src,
                         const float* __restrict__ scale, const float* __restrict__ shift,
                         uint2* __restrict__ dH, uint2* __restrict__ dL, int n4)
{
    int i = blockIdx.x * blockDim.x + threadIdx.x;
    if (i >= n4) return;
    float4 v = src[i];
    int f = (i & 63) * 4;
    float4 sc = *(const float4*)(scale + f);
    float4 sh = *(const float4*)(shift + f);
    v.x = fmaxf(fmaf(v.x, sc.x, sh.x), 0.f);
    v.y = fmaxf(fmaf(v.y, sc.y, sh.y), 0.f);
    v.z = fmaxf(fmaf(v.z, sc.z, sh.z), 0.f);
    v.w = fmaxf(fmaf(v.w, sc.w, sh.w), 0.f);
    uint32_t h0, l0, h1, l1;
    split2(v.x, v.y, h0, l0);
    split2(v.z, v.w, h1, l1);
    dH[i] = make_uint2(h0, h1);
    dL[i] = make_uint2(l0, l1);
}

// ---------------- CSR build ----------------
__global__ void count_k(const int* __restrict__ coli, int* __restrict__ cnt, int E) {
    int i = blockIdx.x * blockDim.x + threadIdx.x;
    int stride = gridDim.x * blockDim.x;
    for (int e = i; e < E; e += stride) atomicAdd(&cnt[coli[e]], 1);
}

__global__ void scan1_k(const int* __restrict__ cnt, int* __restrict__ partial,
                        int* __restrict__ bsum, int N)
{
    __shared__ int sh[SCAN_B];
    int t = threadIdx.x;
    int i = blockIdx.x * SCAN_B + t;
    int v = (i < N) ? cnt[i] : 0;
    sh[t] = v;
    __syncthreads();
#pragma unroll
    for (int off = 1; off < SCAN_B; off <<= 1) {
        int add = (t >= off) ? sh[t - off] : 0;
        __syncthreads();
        sh[t] += add;
        __syncthreads();
    }
    if (i < N) partial[i] = sh[t] - v;
    if (t == SCAN_B - 1) bsum[blockIdx.x] = sh[t];
}

// scan of bsum done redundantly per block; then rowptr/cursor/dis
__global__ void scan3_k(const int* __restrict__ partial, const int* __restrict__ bsum,
                        const int* __restrict__ cnt, int* __restrict__ rowptr,
                        int* __restrict__ cursor, float* __restrict__ dis,
                        int N, int E, int nb)
{
    __shared__ int sh[SCAN_B];
    __shared__ int ex[SCAN_B];
    int t = threadIdx.x;
    int v = (t < nb) ? bsum[t] : 0;
    sh[t] = v;
    __syncthreads();
#pragma unroll
    for (int off = 1; off < SCAN_B; off <<= 1) {
        int add = (t >= off) ? sh[t - off] : 0;
        __syncthreads();
        sh[t] += add;
        __syncthreads();
    }
    ex[t] = sh[t] - v;
    __syncthreads();
    int i = blockIdx.x * SCAN_B + t;
    if (i < N) {
        int rp = partial[i] + ex[i / SCAN_B];
        rowptr[i] = rp;
        cursor[i] = rp;
        dis[i] = rsqrtf((float)(cnt[i] + 1));
    }
    if (i == 0) rowptr[N] = E;
}

__global__ void fill_k(const int* __restrict__ rowi, const int* __restrict__ coli,
                       const float* __restrict__ dis, int* __restrict__ cursor,
                       int2* __restrict__ csr, int E)
{
    int i = blockIdx.x * blockDim.x + threadIdx.x;
    int stride = gridDim.x * blockDim.x;
    for (int e = i; e < E; e += stride) {
        int r = rowi[e], c = coli[e];
        int slot = atomicAdd(&cursor[c], 1);
        csr[slot] = make_int2(r, __float_as_int(dis[r] * dis[c]));
    }
}

// ---------------- tensor-core GEMM (pre-split bf16, cp.async 4-stage) ---------
constexpr int GBM = 128, GBN = 64, GBK = 16;
constexpr int PADW = 12;
constexpr uint32_t OFF_AH = 0;
constexpr uint32_t OFF_AL = 128 * 48;          // 6144
constexpr uint32_t OFF_BH = 12288;
constexpr uint32_t OFF_BL = 12288 + 64 * 48;   // 15360
constexpr uint32_t STAGE  = 18432;
constexpr int NSTAGE = 4;
constexpr int GSMEM = STAGE * NSTAGE;          // 73728

__global__ __launch_bounds__(256, 3)
void gemm_tc_k(const __nv_bfloat16* __restrict__ AH, const __nv_bfloat16* __restrict__ AL,
               const __nv_bfloat16* __restrict__ BtH, const __nv_bfloat16* __restrict__ BtL,
               const float* __restrict__ bias, float* __restrict__ C,
               __nv_bfloat16* __restrict__ CH, __nv_bfloat16* __restrict__ CL,
               int M, int K)
{
    extern __shared__ __align__(16) uint8_t dsm[];
    uint32_t sb = (uint32_t)__cvta_generic_to_shared(dsm);

    int tid = threadIdx.x;
    int wid = tid >> 5, lane = tid & 31;
    int g = lane >> 2, t4 = lane & 3;
    int wm = wid & 3, wn = wid >> 2;

    int rowBase = blockIdx.y * GBM;
    int colBase = blockIdx.x * GBN;

    float acc[2][4][4];
#pragma unroll
    for (int m = 0; m < 2; m++)
#pragma unroll
        for (int na = 0; na < 4; na++)
#pragma unroll
            for (int c = 0; c < 4; c++) acc[m][na][c] = 0.0f;

    int arow = tid >> 1, ahalf = tid & 1;
    uint32_t asz = ((rowBase + arow) < M) ? 16u : 0u;
    const __nv_bfloat16* aphSrc = AH + (size_t)(rowBase + arow) * K + ahalf * 8;
    const __nv_bfloat16* aplSrc = AL + (size_t)(rowBase + arow) * K + ahalf * 8;
    uint32_t aDst = sb + arow * 48 + ahalf * 16;
    int bn = tid >> 2, q = tid & 3;
    const __nv_bfloat16* bphSrc = BtH + (size_t)(colBase + bn) * K + q * 4;
    const __nv_bfloat16* bplSrc = BtL + (size_t)(colBase + bn) * K + q * 4;
    uint32_t bDst = sb + bn * 48 + q * 8;

    int lr = lane & 7;
    int sel = lane >> 3;
    int aRowF  = wm * 32 + (sel & 1) * 8 + lr;
    int aWordF = (sel >> 1) * 4;
    int bRowF  = wn * 32 + (sel >> 1) * 8 + lr;
    int bWordF = (sel & 1) * 4;
    uint32_t aFH = sb + OFF_AH + (aRowF * PADW + aWordF) * 4;
    uint32_t aFL = sb + OFF_AL + (aRowF * PADW + aWordF) * 4;
    uint32_t bFH = sb + OFF_BH + (bRowF * PADW + bWordF) * 4;
    uint32_t bFL = sb + OFF_BL + (bRowF * PADW + bWordF) * 4;
    constexpr uint32_t A_MSTEP = 16 * 48;
    constexpr uint32_t B_PSTEP = 16 * 48;

    auto issue = [&](int t) {
        uint32_t so = (uint32_t)(t % NSTAGE) * STAGE;
        int k0 = t * GBK;
        cp16(aDst + so + OFF_AH, aphSrc + k0, asz);
        cp16(aDst + so + OFF_AL, aplSrc + k0, asz);
        cp8(bDst + so + OFF_BH, bphSrc + k0);
        cp8(bDst + so + OFF_BL, bplSrc + k0);
        CP_COMMIT();
    };

    int nT = K / GBK;
    issue(0);
    if (nT > 1) issue(1);
    if (nT > 2) issue(2);

    for (int t = 0; t < nT; t++) {
        int inflight = (nT - 1 - t < 2) ? (nT - 1 - t) : 2;
        if (inflight == 2)      asm volatile("cp.async.wait_group 2;" ::: "memory");
        else if (inflight == 1) asm volatile("cp.async.wait_group 1;" ::: "memory");
        else                    asm volatile("cp.async.wait_group 0;" ::: "memory");
        __syncthreads();
        if (t + 3 < nT) issue(t + 3);

        uint32_t so = (uint32_t)(t % NSTAGE) * STAGE;
        uint32_t aH[2][4], aL[2][4], bHf[4][2], bLf[4][2];
#pragma unroll
        for (int m = 0; m < 2; m++) {
            ldsm_x4(aH[m][0], aH[m][1], aH[m][2], aH[m][3], aFH + so + m * A_MSTEP);
            ldsm_x4(aL[m][0], aL[m][1], aL[m][2], aL[m][3], aFL + so + m * A_MSTEP);
        }
#pragma unroll
        for (int p = 0; p < 2; p++) {
            ldsm_x4(bHf[2 * p][0], bHf[2 * p][1], bHf[2 * p + 1][0], bHf[2 * p + 1][1],
                    bFH + so + p * B_PSTEP);
            ldsm_x4(bLf[2 * p][0], bLf[2 * p][1], bLf[2 * p + 1][0], bLf[2 * p + 1][1],
                    bFL + so + p * B_PSTEP);
        }

#pragma unroll
        for (int m = 0; m < 2; m++)
#pragma unroll
            for (int na = 0; na < 4; na++) MMA_BF16(acc[m][na], aH[m], bHf[na]);
#pragma unroll
        for (int m = 0; m < 2; m++)
#pragma unroll
            for (int na = 0; na < 4; na++) MMA_BF16(acc[m][na], aH[m], bLf[na]);
#pragma unroll
        for (int m = 0; m < 2; m++)
#pragma unroll
            for (int na = 0; na < 4; na++) MMA_BF16(acc[m][na], aL[m], bHf[na]);
    }

    // epilogue
#pragma unroll
    for (int m = 0; m < 2; m++) {
        int r0 = rowBase + wm * 32 + m * 16 + g;
#pragma unroll
        for (int na = 0; na < 4; na++) {
            int col = colBase + wn * 32 + na * 8 + 2 * t4;
            float b0 = 0.f, b1 = 0.f;
            if (bias) { b0 = bias[col]; b1 = bias[col + 1]; }
            float v0 = acc[m][na][0] + b0, v1 = acc[m][na][1] + b1;
            float v2 = acc[m][na][2] + b0, v3 = acc[m][na][3] + b1;
            if (CH) {
                uint32_t h, l;
                if (r0 < M) {
                    split2(v0, v1, h, l);
                    size_t w = ((size_t)r0 * Hdim + col) >> 1;
                    ((uint32_t*)CH)[w] = h;
                    ((uint32_t*)CL)[w] = l;
                }
                if (r0 + 8 < M) {
                    split2(v2, v3, h, l);
                    size_t w = ((size_t)(r0 + 8) * Hdim + col) >> 1;
                    ((uint32_t*)CH)[w] = h;
                    ((uint32_t*)CL)[w] = l;
                }
            } else {
                if (r0 < M)
                    *(float2*)&C[(size_t)r0 * Hdim + col] = make_float2(v0, v1);
                if (r0 + 8 < M)
                    *(float2*)&C[(size_t)(r0 + 8) * Hdim + col] = make_float2(v2, v3);
            }
        }
    }
}

// ---------------- aggregate + fused BN stats + fused bn_final -----------------
__device__ __forceinline__ void fma4(float4& a, const float4& v, float s) {
    a.x = fmaf(v.x, s, a.x); a.y = fmaf(v.y, s, a.y);
    a.z = fmaf(v.z, s, a.z); a.w = fmaf(v.w, s, a.w);
}

__global__ __launch_bounds__(256)
void aggregate_k(const float* __restrict__ hw, float* __restrict__ agg,
                 const int* __restrict__ rowptr, const int2* __restrict__ csr,
                 const float* __restrict__ dis,
                 const float* __restrict__ convb, double* __restrict__ stats,
                 const float* __restrict__ gamma, const float* __restrict__ beta,
                 float* __restrict__ scaleO, float* __restrict__ shiftO,
                 int* __restrict__ ctr, int N)
{
    __shared__ float4 sh_s[8][32];
    __shared__ float4 sh_q[8][32];
    __shared__ int lastFlag;

    int tid = threadIdx.x;
    int wid = tid >> 5;
    int lane = tid & 31;

    int gw = blockIdx.x * 8 + wid;
    int half = gw & 1;
    int rowOff = half * 32 + lane;

    float4 bseg = ((const float4*)convb)[rowOff];
    float4 tsum = make_float4(0, 0, 0, 0);
    float4 tsq  = make_float4(0, 0, 0, 0);

    int nodeStride = gridDim.x * 4;

    for (int n = gw >> 1; n < N; n += nodeStride) {
        float dn = __ldg(dis + n);
        float sn = dn * dn;
        float4 acc = bseg;
        fma4(acc, ((const float4*)(hw + (size_t)n * Hdim))[rowOff], sn);

        int j  = __ldg(rowptr + n);
        int e1 = __ldg(rowptr + n + 1);

        for (; j + 3 < e1; j += 4) {
            int2 p0 = __ldg(csr + j);
            int2 p1 = __ldg(csr + j + 1);
            int2 p2 = __ldg(csr + j + 2);
            int2 p3 = __ldg(csr + j + 3);
            float4 v0 = ((const float4*)(hw + (size_t)p0.x * Hdim))[rowOff];
            float4 v1 = ((const float4*)(hw + (size_t)p1.x * Hdim))[rowOff];
            float4 v2 = ((const float4*)(hw + (size_t)p2.x * Hdim))[rowOff];
            float4 v3 = ((const float4*)(hw + (size_t)p3.x * Hdim))[rowOff];
            fma4(acc, v0, __int_as_float(p0.y));
            fma4(acc, v1, __int_as_float(p1.y));
            fma4(acc, v2, __int_as_float(p2.y));
            fma4(acc, v3, __int_as_float(p3.y));
        }
        for (; j < e1; j++) {
            int2 p = __ldg(csr + j);
            float4 v = ((const float4*)(hw + (size_t)p.x * Hdim))[rowOff];
            fma4(acc, v, __int_as_float(p.y));
        }

        ((float4*)(agg + (size_t)n * Hdim))[rowOff] = acc;

        tsum.x += acc.x; tsum.y += acc.y; tsum.z += acc.z; tsum.w += acc.w;
        tsq.x = fmaf(acc.x, acc.x, tsq.x); tsq.y = fmaf(acc.y, acc.y, tsq.y);
        tsq.z = fmaf(acc.z, acc.z, tsq.z); tsq.w = fmaf(acc.w, acc.w, tsq.w);
    }

    sh_s[wid][lane] = tsum;
    sh_q[wid][lane] = tsq;
    __syncthreads();

    int f = tid;
    int f4 = f >> 2, comp = f & 3;
    int hf = f4 >> 5, l = f4 & 31;
    float s = 0.f, q = 0.f;
#pragma unroll
    for (int k = 0; k < 4; k++) {
        int w = hf + 2 * k;
        s += ((const float*)&sh_s[w][l])[comp];
        q += ((const float*)&sh_q[w][l])[comp];
    }
    atomicAdd(&stats[f], (double)s);
    atomicAdd(&stats[Hdim + f], (double)q);

    // ---- last block computes scale/shift ----
    __threadfence();
    __syncthreads();
    if (tid == 0) lastFlag = (atomicAdd(ctr, 1) == (int)gridDim.x - 1);
    __syncthreads();
    if (lastFlag) {
        double sm = __ldcg(&stats[f]);
        double sq = __ldcg(&stats[Hdim + f]);
        double mean = sm / N;
        double var = sq / N - mean * mean;
        float sc = gamma[f] * rsqrtf((float)var + 1e-5f);
        scaleO[f] = sc;
        shiftO[f] = beta[f] - (float)mean * sc;
    }
}

// ---------------- global add pool with fused BN affine + ReLU ----------------
__global__ void pool_k(const float* __restrict__ h, const int* __restrict__ batch,
                       const float* __restrict__ scale, const float* __restrict__ shift,
                       float* __restrict__ g, int N)
{
    constexpr int CH = 256;
    int f = threadIdx.x;
    int r0 = blockIdx.x * CH;
    int r1 = min(N, r0 + CH);
    if (r0 >= N) return;
    float sc = scale[f], sh = shift[f];
    int cur = batch[r0];
    float s = 0.f;
    for (int r = r0; r < r1; r++) {
        int b = batch[r];
        if (b != cur) {
            atomicAdd(&g[cur * Hdim + f], s);
            s = 0.f;
            cur = b;
        }
        s += fmaxf(fmaf(h[(size_t)r * Hdim + f], sc, sh), 0.f);
    }
    atomicAdd(&g[cur * Hdim + f], s);
}

// ---------------- MLP head ----------------
__global__ void head_k(const float* __restrict__ g, const float* __restrict__ w1,
                       const float* __restrict__ b1, const float* __restrict__ w2,
                       const float* __restrict__ b2, float* __restrict__ out)
{
    __shared__ float gs[Hdim];
    __shared__ float zs[HD2];
    int b = blockIdx.x;
    int t = threadIdx.x;
    gs[t]       = g[b * Hdim + t];
    gs[t + 128] = g[b * Hdim + t + 128];
    __syncthreads();
    float acc = b1[t];
    for (int k = 0; k < Hdim; k++) acc = fmaf(gs[k], w1[k * HD2 + t], acc);
    zs[t] = fmaxf(acc, 0.f);
    __syncthreads();
    if (t < OUTdim) {
        float o = b2[t];
        for (int k = 0; k < HD2; k++) o = fmaf(zs[k], w2[k * OUTdim + t], o);
        out[b * OUTdim + t] = o;
    }
}

// ---------------- launch ----------------
extern "C" void kernel_launch(void* const* d_in, const int* in_sizes, int n_in,
                              void* d_out, int out_size)
{
    const float* x       = (const float*)d_in[0];
    const int*   ei      = (const int*)d_in[1];
    const int*   batch   = (const int*)d_in[2];
    const float* node_w  = (const float*)d_in[3];
    const float* node_b  = (const float*)d_in[4];
    const float* conv_w  = (const float*)d_in[5];
    const float* conv_b  = (const float*)d_in[6];
    const float* bn_g    = (const float*)d_in[7];
    const float* bn_b    = (const float*)d_in[8];
    const float* head_w1 = (const float*)d_in[9];
    const float* head_b1 = (const float*)d_in[10];
    const float* head_w2 = (const float*)d_in[11];
    const float* head_b2 = (const float*)d_in[12];
    float* out = (float*)d_out;

    int N = in_sizes[0] / INdim;
    int E = in_sizes[1] / 2;
    const int* rowi = ei;
    const int* coli = ei + E;

    float *bufA, *bufB, *dis, *scale, *shift, *pool;
    int *cnt, *rowptr, *cursor, *partial, *bsum, *ctr;
    int2* csr;
    double* stats;
    __nv_bfloat16 *BtH, *BtL, *pAH, *pAL, *qAH, *qAL;
    cudaGetSymbolAddress((void**)&bufA, g_bufA);
    cudaGetSymbolAddress((void**)&bufB, g_bufB);
    cudaGetSymbolAddress((void**)&dis, g_dis);
    cudaGetSymbolAddress((void**)&cnt, g_cnt);
    cudaGetSymbolAddress((void**)&rowptr, g_rowptr);
    cudaGetSymbolAddress((void**)&cursor, g_cursor);
    cudaGetSymbolAddress((void**)&partial, g_partial);
    cudaGetSymbolAddress((void**)&bsum, g_bsum);
    cudaGetSymbolAddress((void**)&csr, g_csr);
    cudaGetSymbolAddress((void**)&stats, g_stats);
    cudaGetSymbolAddress((void**)&scale, g_scale);
    cudaGetSymbolAddress((void**)&shift, g_shift);
    cudaGetSymbolAddress((void**)&pool, g_pool);
    cudaGetSymbolAddress((void**)&ctr, g_ctr);
    cudaGetSymbolAddress((void**)&BtH, g_BtH);
    cudaGetSymbolAddress((void**)&BtL, g_BtL);
    cudaGetSymbolAddress((void**)&pAH, g_pAH);
    cudaGetSymbolAddress((void**)&pAL, g_pAL);
    cudaGetSymbolAddress((void**)&qAH, g_qAH);
    cudaGetSymbolAddress((void**)&qAL, g_qAL);

    static int smemSet = 0;
    if (!smemSet) {
        cudaFuncSetAttribute(gemm_tc_k, cudaFuncAttributeMaxDynamicSharedMemorySize, GSMEM);
        smemSet = 1;
    }

    int nblk1 = (N + SCAN_B - 1) / SCAN_B;
    dim3 ggrid(Hdim / GBN, (N + GBM - 1) / GBM);   // (4, 391)
    int aggBlocks = 592;

    // 1: prolog  2: node gemm  3: count  4: conv gemm l0 (profiled slot)
    prolog_k<<<(N * 16 + 255) / 256, 256>>>(node_w, conv_w, (const float4*)x,
                                            (uint2*)pAH, (uint2*)pAL,
                                            cnt, stats, pool, ctr, N);
    gemm_tc_k<<<ggrid, 256, GSMEM>>>(pAH, pAL, BtH + NODE_OFF, BtL + NODE_OFF,
                                     node_b, nullptr, qAH, qAL, N, INdim);
    count_k<<<592, 256>>>(coli, cnt, E);
    gemm_tc_k<<<ggrid, 256, GSMEM>>>(qAH, qAL, BtH + CONV_OFF, BtL + CONV_OFF,
                                     nullptr, bufB, nullptr, nullptr, N, Hdim);

    // CSR build tail
    scan1_k<<<nblk1, SCAN_B>>>(cnt, partial, bsum, N);
    scan3_k<<<nblk1, SCAN_B>>>(partial, bsum, cnt, rowptr, cursor, dis, N, E, nblk1);
    fill_k<<<592, 256>>>(rowi, coli, dis, cursor, csr, E);

    // layer 0 tail (aggregate computes scale/shift for layer 0)
    aggregate_k<<<aggBlocks, 256>>>(bufB, bufA, rowptr, csr, dis, conv_b, stats,
                                    bn_g, bn_b, scale, shift, ctr, N);

    // layers 1..2
    for (int l = 1; l < NLAY; l++) {
        asplit_k<<<(N * 64 + 255) / 256, 256>>>((const float4*)bufA,
                                                scale + (l - 1) * Hdim, shift + (l - 1) * Hdim,
                                                (uint2*)pAH, (uint2*)pAL, N * 64);
        gemm_tc_k<<<ggrid, 256, GSMEM>>>(pAH, pAL,
                                         BtH + CONV_OFF + l * 65536, BtL + CONV_OFF + l * 65536,
                                         nullptr, bufB, nullptr, nullptr, N, Hdim);
        aggregate_k<<<aggBlocks, 256>>>(bufB, bufA, rowptr, csr, dis,
                                        conv_b + l * Hdim, stats + l * 2 * Hdim,
                                        bn_g + l * Hdim, bn_b + l * Hdim,
                                        scale + l * Hdim, shift + l * Hdim,
                                        ctr + l, N);
    }

    // pool (applies layer-2 BN affine + relu) + head
    pool_k<<<(N + 255) / 256, 256>>>(bufA, batch, scale + 2 * Hdim, shift + 2 * Hdim,
                                     pool, N);
    head_k<<<NGRAPH, HD2>>>(pool, head_w1, head_b1, head_w2, head_b2, out);
}

// round 14
// speedup vs baseline: 1.0256x; 1.0256x over previous
#include <cuda_runtime.h>
#include <cuda_bf16.h>
#include <cstdint>
#include <math.h>

// ---------------- problem constants ----------------
constexpr int Hdim   = 256;
constexpr int INdim  = 64;
constexpr int HD2    = 128;
constexpr int OUTdim = 12;
constexpr int NLAY   = 3;
constexpr int NGRAPH = 64;
constexpr int NMAX   = 50000;
constexpr int EMAX   = 600000;
constexpr int SCAN_B = 512;
constexpr int MAXBLK1 = (NMAX + SCAN_B - 1) / SCAN_B;

// weight scratch: bf16 split + transposed [N][K]
constexpr int NODE_OFF = 0;                      // 256 x 64
constexpr int CONV_OFF = 256 * 64;               // 3 x (256 x 256)
constexpr int WTOT     = CONV_OFF + 3 * 256 * 256;

// ---------------- scratch (device globals, no allocation) ----------------
__device__ float  g_bufA[(size_t)NMAX * Hdim];
__device__ float  g_bufB[(size_t)NMAX * Hdim];
__device__ float  g_dis[NMAX];
__device__ int    g_cnt[NMAX];
__device__ int    g_rowptr[NMAX + 1];
__device__ int    g_cursor[NMAX];
__device__ int    g_partial[NMAX];
__device__ int    g_bsum[MAXBLK1 + 1];
__device__ int2   g_csr[EMAX];
__device__ double g_stats[NLAY * 2 * Hdim];
__device__ float  g_scale[NLAY * Hdim];
__device__ float  g_shift[NLAY * Hdim];
__device__ float  g_pool[NGRAPH * Hdim];
__device__ int    g_ctr[8];
__device__ __nv_bfloat16 g_BtH[WTOT];
__device__ __nv_bfloat16 g_BtL[WTOT];
__device__ __nv_bfloat16 g_pAH[(size_t)NMAX * Hdim];
__device__ __nv_bfloat16 g_pAL[(size_t)NMAX * Hdim];
__device__ __nv_bfloat16 g_qAH[(size_t)NMAX * Hdim];
__device__ __nv_bfloat16 g_qAL[(size_t)NMAX * Hdim];

// ---------------- helpers ----------------
__device__ __forceinline__ uint32_t packbf2(float hi, float lo) {
    uint32_t d;
    asm("cvt.rn.bf16x2.f32 %0, %1, %2;" : "=r"(d) : "f"(hi), "f"(lo));
    return d;
}

__device__ __forceinline__ void split2(float x0, float x1, uint32_t& h, uint32_t& l) {
    h = packbf2(x1, x0);
    float f0 = __uint_as_float(h << 16);
    float f1 = __uint_as_float(h & 0xFFFF0000u);
    l = packbf2(x1 - f1, x0 - f0);
}

#define MMA_BF16(d, a, b)                                                       \
    asm volatile("mma.sync.aligned.m16n8k16.row.col.f32.bf16.bf16.f32 "        \
                 "{%0,%1,%2,%3},{%4,%5,%6,%7},{%8,%9},{%0,%1,%2,%3};"          \
                 : "+f"(d[0]), "+f"(d[1]), "+f"(d[2]), "+f"(d[3])              \
                 : "r"(a[0]), "r"(a[1]), "r"(a[2]), "r"(a[3]),                 \
                   "r"(b[0]), "r"(b[1]))

__device__ __forceinline__ void ldsm_x4(uint32_t& r0, uint32_t& r1,
                                        uint32_t& r2, uint32_t& r3, uint32_t addr) {
    asm volatile("ldmatrix.sync.aligned.m8n8.x4.shared.b16 {%0,%1,%2,%3}, [%4];"
                 : "=r"(r0), "=r"(r1), "=r"(r2), "=r"(r3) : "r"(addr));
}

__device__ __forceinline__ void cp16(uint32_t dst, const void* src, uint32_t sz) {
    asm volatile("cp.async.cg.shared.global [%0], [%1], 16, %2;"
                 :: "r"(dst), "l"(src), "r"(sz) : "memory");
}
#define CP_COMMIT() asm volatile("cp.async.commit_group;" ::: "memory")

// ---------------- prolog: zero + weight split + x split (one kernel) ----------
__global__ void prolog_k(const float* __restrict__ node_w, const float* __restrict__ conv_w,
                         const float4* __restrict__ x,
                         uint2* __restrict__ xH, uint2* __restrict__ xL,
                         int* __restrict__ cnt, double* __restrict__ stats,
                         float* __restrict__ pool, int* __restrict__ ctr, int N)
{
    int i = blockIdx.x * blockDim.x + threadIdx.x;
    if (i < N * 16) {
        float4 v = x[i];
        uint32_t h0, l0, h1, l1;
        split2(v.x, v.y, h0, l0);
        split2(v.z, v.w, h1, l1);
        xH[i] = make_uint2(h0, h1);
        xL[i] = make_uint2(l0, l1);
    }
    if (i < WTOT) {
        float v;
        if (i < CONV_OFF) {
            int n = i / INdim, k = i % INdim;
            v = node_w[k * Hdim + n];
        } else {
            int rel = i - CONV_OFF;
            int l = rel >> 16;
            int r2 = rel & 65535;
            int n = r2 >> 8, k = r2 & 255;
            v = conv_w[l * 65536 + k * Hdim + n];
        }
        __nv_bfloat16 h = __float2bfloat16(v);
        __nv_bfloat16 lo = __float2bfloat16(v - __bfloat162float(h));
        g_BtH[i] = h;
        g_BtL[i] = lo;
    }
    if (i < N) cnt[i] = 0;
    if (i < NLAY * 2 * Hdim) stats[i] = 0.0;
    if (i < NGRAPH * Hdim) pool[i] = 0.0f;
    if (i < 8) ctr[i] = 0;
}

// ---------------- activation split (+ BN affine + relu) ----------------------
__global__ void asplit_k(const float4* __restrict__ src,
                         const float* __restrict__ scale, const float* __restrict__ shift,
                         uint2* __restrict__ dH, uint2* __restrict__ dL, int n4)
{
    int i = blockIdx.x * blockDim.x + threadIdx.x;
    if (i >= n4) return;
    float4 v = src[i];
    int f = (i & 63) * 4;
    float4 sc = *(const float4*)(scale + f);
    float4 sh = *(const float4*)(shift + f);
    v.x = fmaxf(fmaf(v.x, sc.x, sh.x), 0.f);
    v.y = fmaxf(fmaf(v.y, sc.y, sh.y), 0.f);
    v.z = fmaxf(fmaf(v.z, sc.z, sh.z), 0.f);
    v.w = fmaxf(fmaf(v.w, sc.w, sh.w), 0.f);
    uint32_t h0, l0, h1, l1;
    split2(v.x, v.y, h0, l0);
    split2(v.z, v.w, h1, l1);
    dH[i] = make_uint2(h0, h1);
    dL[i] = make_uint2(l0, l1);
}

// ---------------- CSR build (int4-vectorized) ----------------
__global__ void count_k(const int4* __restrict__ coli4, int* __restrict__ cnt, int E4) {
    int i = blockIdx.x * blockDim.x + threadIdx.x;
    int stride = gridDim.x * blockDim.x;
    for (int e = i; e < E4; e += stride) {
        int4 c = coli4[e];
        atomicAdd(&cnt[c.x], 1);
        atomicAdd(&cnt[c.y], 1);
        atomicAdd(&cnt[c.z], 1);
        atomicAdd(&cnt[c.w], 1);
    }
}

__global__ void scan1_k(const int* __restrict__ cnt, int* __restrict__ partial,
                        int* __restrict__ bsum, int N)
{
    __shared__ int sh[SCAN_B];
    int t = threadIdx.x;
    int i = blockIdx.x * SCAN_B + t;
    int v = (i < N) ? cnt[i] : 0;
    sh[t] = v;
    __syncthreads();
#pragma unroll
    for (int off = 1; off < SCAN_B; off <<= 1) {
        int add = (t >= off) ? sh[t - off] : 0;
        __syncthreads();
        sh[t] += add;
        __syncthreads();
    }
    if (i < N) partial[i] = sh[t] - v;
    if (t == SCAN_B - 1) bsum[blockIdx.x] = sh[t];
}

__global__ void scan3_k(const int* __restrict__ partial, const int* __restrict__ bsum,
                        const int* __restrict__ cnt, int* __restrict__ rowptr,
                        int* __restrict__ cursor, float* __restrict__ dis,
                        int N, int E, int nb)
{
    __shared__ int sh[SCAN_B];
    __shared__ int ex[SCAN_B];
    int t = threadIdx.x;
    int v = (t < nb) ? bsum[t] : 0;
    sh[t] = v;
    __syncthreads();
#pragma unroll
    for (int off = 1; off < SCAN_B; off <<= 1) {
        int add = (t >= off) ? sh[t - off] : 0;
        __syncthreads();
        sh[t] += add;
        __syncthreads();
    }
    ex[t] = sh[t] - v;
    __syncthreads();
    int i = blockIdx.x * SCAN_B + t;
    if (i < N) {
        int rp = partial[i] + ex[i / SCAN_B];
        rowptr[i] = rp;
        cursor[i] = rp;
        dis[i] = rsqrtf((float)(cnt[i] + 1));
    }
    if (i == 0) rowptr[N] = E;
}

__global__ void fill_k(const int4* __restrict__ rowi4, const int4* __restrict__ coli4,
                       const float* __restrict__ dis, int* __restrict__ cursor,
                       int2* __restrict__ csr, int E4)
{
    int i = blockIdx.x * blockDim.x + threadIdx.x;
    int stride = gridDim.x * blockDim.x;
    for (int e = i; e < E4; e += stride) {
        int4 r4 = rowi4[e];
        int4 c4 = coli4[e];
        int slot;
        slot = atomicAdd(&cursor[c4.x], 1);
        csr[slot] = make_int2(r4.x, __float_as_int(dis[r4.x] * dis[c4.x]));
        slot = atomicAdd(&cursor[c4.y], 1);
        csr[slot] = make_int2(r4.y, __float_as_int(dis[r4.y] * dis[c4.y]));
        slot = atomicAdd(&cursor[c4.z], 1);
        csr[slot] = make_int2(r4.z, __float_as_int(dis[r4.z] * dis[c4.z]));
        slot = atomicAdd(&cursor[c4.w], 1);
        csr[slot] = make_int2(r4.w, __float_as_int(dis[r4.w] * dis[c4.w]));
    }
}

// ---------------- tensor-core GEMM (pre-split bf16, cp.async 4-stage) ---------
// Block tile 128x128, 8 warps (4m x 2n), warp tile 32x64 (2 n-batches of 32).
constexpr int GBM = 128, GBN = 128, GBK = 16;
constexpr int PADW = 12;
constexpr uint32_t OFF_AH = 0;
constexpr uint32_t OFF_AL = 6144;
constexpr uint32_t OFF_BH = 12288;
constexpr uint32_t OFF_BL = 18432;
constexpr uint32_t STAGE  = 24576;
constexpr int NSTAGE = 4;
constexpr int GSMEM = STAGE * NSTAGE;          // 98304

__global__ __launch_bounds__(256, 2)
void gemm_tc_k(const __nv_bfloat16* __restrict__ AH, const __nv_bfloat16* __restrict__ AL,
               const __nv_bfloat16* __restrict__ BtH, const __nv_bfloat16* __restrict__ BtL,
               const float* __restrict__ bias, float* __restrict__ C,
               __nv_bfloat16* __restrict__ CH, __nv_bfloat16* __restrict__ CL,
               int M, int K)
{
    extern __shared__ __align__(16) uint8_t dsm[];
    uint32_t sb = (uint32_t)__cvta_generic_to_shared(dsm);

    int tid = threadIdx.x;
    int wid = tid >> 5, lane = tid & 31;
    int g = lane >> 2, t4 = lane & 3;
    int wm = wid & 3, wn = wid >> 2;

    int rowBase = blockIdx.y * GBM;
    int colBase = blockIdx.x * GBN;

    float acc[2][8][4];
#pragma unroll
    for (int m = 0; m < 2; m++)
#pragma unroll
        for (int na = 0; na < 8; na++)
#pragma unroll
            for (int c = 0; c < 4; c++) acc[m][na][c] = 0.0f;

    // staging: A thread -> row tid>>1, 8 bf16 (16B) at half (tid&1)*8
    int arow = tid >> 1, ahalf = tid & 1;
    uint32_t asz = ((rowBase + arow) < M) ? 16u : 0u;
    const __nv_bfloat16* aphSrc = AH + (size_t)(rowBase + arow) * K + ahalf * 8;
    const __nv_bfloat16* aplSrc = AL + (size_t)(rowBase + arow) * K + ahalf * 8;
    uint32_t aDst = sb + arow * 48 + ahalf * 16;
    // B: thread -> n tid>>1, half tid&1 (128 n rows x 2 halves)
    int bn = tid >> 1, bhalf = tid & 1;
    const __nv_bfloat16* bphSrc = BtH + (size_t)(colBase + bn) * K + bhalf * 8;
    const __nv_bfloat16* bplSrc = BtL + (size_t)(colBase + bn) * K + bhalf * 8;
    uint32_t bDst = sb + bn * 48 + bhalf * 16;

    // ldmatrix fragment lane addressing
    int lr = lane & 7;
    int sel = lane >> 3;
    int aRowF  = wm * 32 + (sel & 1) * 8 + lr;
    int aWordF = (sel >> 1) * 4;
    int bRowF  = wn * 64 + (sel >> 1) * 8 + lr;
    int bWordF = (sel & 1) * 4;
    uint32_t aFH = sb + OFF_AH + (aRowF * PADW + aWordF) * 4;
    uint32_t aFL = sb + OFF_AL + (aRowF * PADW + aWordF) * 4;
    uint32_t bFH = sb + OFF_BH + (bRowF * PADW + bWordF) * 4;
    uint32_t bFL = sb + OFF_BL + (bRowF * PADW + bWordF) * 4;
    constexpr uint32_t A_MSTEP = 16 * 48;
    constexpr uint32_t B_PSTEP = 16 * 48;

    auto issue = [&](int t) {
        uint32_t so = (uint32_t)(t % NSTAGE) * STAGE;
        int k0 = t * GBK;
        cp16(aDst + so + OFF_AH, aphSrc + k0, asz);
        cp16(aDst + so + OFF_AL, aplSrc + k0, asz);
        cp16(bDst + so + OFF_BH, bphSrc + k0, 16u);
        cp16(bDst + so + OFF_BL, bplSrc + k0, 16u);
        CP_COMMIT();
    };

    int nT = K / GBK;
    issue(0);
    if (nT > 1) issue(1);
    if (nT > 2) issue(2);

    for (int t = 0; t < nT; t++) {
        int inflight = (nT - 1 - t < 2) ? (nT - 1 - t) : 2;
        if (inflight == 2)      asm volatile("cp.async.wait_group 2;" ::: "memory");
        else if (inflight == 1) asm volatile("cp.async.wait_group 1;" ::: "memory");
        else                    asm volatile("cp.async.wait_group 0;" ::: "memory");
        __syncthreads();
        if (t + 3 < nT) issue(t + 3);

        uint32_t so = (uint32_t)(t % NSTAGE) * STAGE;
        uint32_t aH[2][4], aL[2][4];
#pragma unroll
        for (int m = 0; m < 2; m++) {
            ldsm_x4(aH[m][0], aH[m][1], aH[m][2], aH[m][3], aFH + so + m * A_MSTEP);
            ldsm_x4(aL[m][0], aL[m][1], aL[m][2], aL[m][3], aFL + so + m * A_MSTEP);
        }
#pragma unroll
        for (int bb = 0; bb < 2; bb++) {
            uint32_t bHf[4][2], bLf[4][2];
#pragma unroll
            for (int p2 = 0; p2 < 2; p2++) {
                int p = bb * 2 + p2;
                ldsm_x4(bHf[2 * p2][0], bHf[2 * p2][1], bHf[2 * p2 + 1][0], bHf[2 * p2 + 1][1],
                        bFH + so + p * B_PSTEP);
                ldsm_x4(bLf[2 * p2][0], bLf[2 * p2][1], bLf[2 * p2 + 1][0], bLf[2 * p2 + 1][1],
                        bFL + so + p * B_PSTEP);
            }
#pragma unroll
            for (int m = 0; m < 2; m++)
#pragma unroll
                for (int nn = 0; nn < 4; nn++) MMA_BF16(acc[m][bb * 4 + nn], aH[m], bHf[nn]);
#pragma unroll
            for (int m = 0; m < 2; m++)
#pragma unroll
                for (int nn = 0; nn < 4; nn++) MMA_BF16(acc[m][bb * 4 + nn], aH[m], bLf[nn]);
#pragma unroll
            for (int m = 0; m < 2; m++)
#pragma unroll
                for (int nn = 0; nn < 4; nn++) MMA_BF16(acc[m][bb * 4 + nn], aL[m], bHf[nn]);
        }
    }

    // epilogue
#pragma unroll
    for (int m = 0; m < 2; m++) {
        int r0 = rowBase + wm * 32 + m * 16 + g;
#pragma unroll
        for (int na = 0; na < 8; na++) {
            int col = colBase + wn * 64 + na * 8 + 2 * t4;
            float b0 = 0.f, b1 = 0.f;
            if (bias) { b0 = bias[col]; b1 = bias[col + 1]; }
            float v0 = acc[m][na][0] + b0, v1 = acc[m][na][1] + b1;
            float v2 = acc[m][na][2] + b0, v3 = acc[m][na][3] + b1;
            if (CH) {
                uint32_t h, l;
                if (r0 < M) {
                    split2(v0, v1, h, l);
                    size_t w = ((size_t)r0 * Hdim + col) >> 1;
                    ((uint32_t*)CH)[w] = h;
                    ((uint32_t*)CL)[w] = l;
                }
                if (r0 + 8 < M) {
                    split2(v2, v3, h, l);
                    size_t w = ((size_t)(r0 + 8) * Hdim + col) >> 1;
                    ((uint32_t*)CH)[w] = h;
                    ((uint32_t*)CL)[w] = l;
                }
            } else {
                if (r0 < M)
                    *(float2*)&C[(size_t)r0 * Hdim + col] = make_float2(v0, v1);
                if (r0 + 8 < M)
                    *(float2*)&C[(size_t)(r0 + 8) * Hdim + col] = make_float2(v2, v3);
            }
        }
    }
}

// ---------------- aggregate + fused BN stats + fused bn_final -----------------
__device__ __forceinline__ void fma4(float4& a, const float4& v, float s) {
    a.x = fmaf(v.x, s, a.x); a.y = fmaf(v.y, s, a.y);
    a.z = fmaf(v.z, s, a.z); a.w = fmaf(v.w, s, a.w);
}

__global__ __launch_bounds__(256)
void aggregate_k(const float* __restrict__ hw, float* __restrict__ agg,
                 const int* __restrict__ rowptr, const int2* __restrict__ csr,
                 const float* __restrict__ dis,
                 const float* __restrict__ convb, double* __restrict__ stats,
                 const float* __restrict__ gamma, const float* __restrict__ beta,
                 float* __restrict__ scaleO, float* __restrict__ shiftO,
                 int* __restrict__ ctr, int N)
{
    __shared__ float4 sh_s[8][32];
    __shared__ float4 sh_q[8][32];
    __shared__ int lastFlag;

    int tid = threadIdx.x;
    int wid = tid >> 5;
    int lane = tid & 31;

    int gw = blockIdx.x * 8 + wid;
    int half = gw & 1;
    int rowOff = half * 32 + lane;

    float4 bseg = ((const float4*)convb)[rowOff];
    float4 tsum = make_float4(0, 0, 0, 0);
    float4 tsq  = make_float4(0, 0, 0, 0);

    int nodeStride = gridDim.x * 4;

    for (int n = gw >> 1; n < N; n += nodeStride) {
        float dn = __ldg(dis + n);
        float sn = dn * dn;
        float4 acc = bseg;
        fma4(acc, ((const float4*)(hw + (size_t)n * Hdim))[rowOff], sn);

        int j  = __ldg(rowptr + n);
        int e1 = __ldg(rowptr + n + 1);

        for (; j + 3 < e1; j += 4) {
            int2 p0 = __ldg(csr + j);
            int2 p1 = __ldg(csr + j + 1);
            int2 p2 = __ldg(csr + j + 2);
            int2 p3 = __ldg(csr + j + 3);
            float4 v0 = ((const float4*)(hw + (size_t)p0.x * Hdim))[rowOff];
            float4 v1 = ((const float4*)(hw + (size_t)p1.x * Hdim))[rowOff];
            float4 v2 = ((const float4*)(hw + (size_t)p2.x * Hdim))[rowOff];
            float4 v3 = ((const float4*)(hw + (size_t)p3.x * Hdim))[rowOff];
            fma4(acc, v0, __int_as_float(p0.y));
            fma4(acc, v1, __int_as_float(p1.y));
            fma4(acc, v2, __int_as_float(p2.y));
            fma4(acc, v3, __int_as_float(p3.y));
        }
        for (; j < e1; j++) {
            int2 p = __ldg(csr + j);
            float4 v = ((const float4*)(hw + (size_t)p.x * Hdim))[rowOff];
            fma4(acc, v, __int_as_float(p.y));
        }

        ((float4*)(agg + (size_t)n * Hdim))[rowOff] = acc;

        tsum.x += acc.x; tsum.y += acc.y; tsum.z += acc.z; tsum.w += acc.w;
        tsq.x = fmaf(acc.x, acc.x, tsq.x); tsq.y = fmaf(acc.y, acc.y, tsq.y);
        tsq.z = fmaf(acc.z, acc.z, tsq.z); tsq.w = fmaf(acc.w, acc.w, tsq.w);
    }

    sh_s[wid][lane] = tsum;
    sh_q[wid][lane] = tsq;
    __syncthreads();

    int f = tid;
    int f4 = f >> 2, comp = f & 3;
    int hf = f4 >> 5, l = f4 & 31;
    float s = 0.f, q = 0.f;
#pragma unroll
    for (int k = 0; k < 4; k++) {
        int w = hf + 2 * k;
        s += ((const float*)&sh_s[w][l])[comp];
        q += ((const float*)&sh_q[w][l])[comp];
    }
    atomicAdd(&stats[f], (double)s);
    atomicAdd(&stats[Hdim + f], (double)q);

    __threadfence();
    __syncthreads();
    if (tid == 0) lastFlag = (atomicAdd(ctr, 1) == (int)gridDim.x - 1);
    __syncthreads();
    if (lastFlag) {
        double sm = __ldcg(&stats[f]);
        double sq = __ldcg(&stats[Hdim + f]);
        double mean = sm / N;
        double var = sq / N - mean * mean;
        float sc = gamma[f] * rsqrtf((float)var + 1e-5f);
        scaleO[f] = sc;
        shiftO[f] = beta[f] - (float)mean * sc;
    }
}

// ---------------- global add pool with fused BN affine + ReLU ----------------
__global__ void pool_k(const float* __restrict__ h, const int* __restrict__ batch,
                       const float* __restrict__ scale, const float* __restrict__ shift,
                       float* __restrict__ g, int N)
{
    constexpr int CH = 256;
    int f = threadIdx.x;
    int r0 = blockIdx.x * CH;
    int r1 = min(N, r0 + CH);
    if (r0 >= N) return;
    float sc = scale[f], sh = shift[f];
    int cur = batch[r0];
    float s = 0.f;
    for (int r = r0; r < r1; r++) {
        int b = batch[r];
        if (b != cur) {
            atomicAdd(&g[cur * Hdim + f], s);
            s = 0.f;
            cur = b;
        }
        s += fmaxf(fmaf(h[(size_t)r * Hdim + f], sc, sh), 0.f);
    }
    atomicAdd(&g[cur * Hdim + f], s);
}

// ---------------- MLP head ----------------
__global__ void head_k(const float* __restrict__ g, const float* __restrict__ w1,
                       const float* __restrict__ b1, const float* __restrict__ w2,
                       const float* __restrict__ b2, float* __restrict__ out)
{
    __shared__ float gs[Hdim];
    __shared__ float zs[HD2];
    int b = blockIdx.x;
    int t = threadIdx.x;
    gs[t]       = g[b * Hdim + t];
    gs[t + 128] = g[b * Hdim + t + 128];
    __syncthreads();
    float acc = b1[t];
    for (int k = 0; k < Hdim; k++) acc = fmaf(gs[k], w1[k * HD2 + t], acc);
    zs[t] = fmaxf(acc, 0.f);
    __syncthreads();
    if (t < OUTdim) {
        float o = b2[t];
        for (int k = 0; k < HD2; k++) o = fmaf(zs[k], w2[k * OUTdim + t], o);
        out[b * OUTdim + t] = o;
    }
}

// ---------------- launch ----------------
extern "C" void kernel_launch(void* const* d_in, const int* in_sizes, int n_in,
                              void* d_out, int out_size)
{
    const float* x       = (const float*)d_in[0];
    const int*   ei      = (const int*)d_in[1];
    const int*   batch   = (const int*)d_in[2];
    const float* node_w  = (const float*)d_in[3];
    const float* node_b  = (const float*)d_in[4];
    const float* conv_w  = (const float*)d_in[5];
    const float* conv_b  = (const float*)d_in[6];
    const float* bn_g    = (const float*)d_in[7];
    const float* bn_b    = (const float*)d_in[8];
    const float* head_w1 = (const float*)d_in[9];
    const float* head_b1 = (const float*)d_in[10];
    const float* head_w2 = (const float*)d_in[11];
    const float* head_b2 = (const float*)d_in[12];
    float* out = (float*)d_out;

    int N = in_sizes[0] / INdim;
    int E = in_sizes[1] / 2;
    const int* rowi = ei;
    const int* coli = ei + E;

    float *bufA, *bufB, *dis, *scale, *shift, *pool;
    int *cnt, *rowptr, *cursor, *partial, *bsum, *ctr;
    int2* csr;
    double* stats;
    __nv_bfloat16 *BtH, *BtL, *pAH, *pAL, *qAH, *qAL;
    cudaGetSymbolAddress((void**)&bufA, g_bufA);
    cudaGetSymbolAddress((void**)&bufB, g_bufB);
    cudaGetSymbolAddress((void**)&dis, g_dis);
    cudaGetSymbolAddress((void**)&cnt, g_cnt);
    cudaGetSymbolAddress((void**)&rowptr, g_rowptr);
    cudaGetSymbolAddress((void**)&cursor, g_cursor);
    cudaGetSymbolAddress((void**)&partial, g_partial);
    cudaGetSymbolAddress((void**)&bsum, g_bsum);
    cudaGetSymbolAddress((void**)&csr, g_csr);
    cudaGetSymbolAddress((void**)&stats, g_stats);
    cudaGetSymbolAddress((void**)&scale, g_scale);
    cudaGetSymbolAddress((void**)&shift, g_shift);
    cudaGetSymbolAddress((void**)&pool, g_pool);
    cudaGetSymbolAddress((void**)&ctr, g_ctr);
    cudaGetSymbolAddress((void**)&BtH, g_BtH);
    cudaGetSymbolAddress((void**)&BtL, g_BtL);
    cudaGetSymbolAddress((void**)&pAH, g_pAH);
    cudaGetSymbolAddress((void**)&pAL, g_pAL);
    cudaGetSymbolAddress((void**)&qAH, g_qAH);
    cudaGetSymbolAddress((void**)&qAL, g_qAL);

    static int smemSet = 0;
    if (!smemSet) {
        cudaFuncSetAttribute(gemm_tc_k, cudaFuncAttributeMaxDynamicSharedMemorySize, GSMEM);
        smemSet = 1;
    }

    int nblk1 = (N + SCAN_B - 1) / SCAN_B;
    dim3 ggrid(Hdim / GBN, (N + GBM - 1) / GBM);   // (2, 391)
    int aggBlocks = 592;
    int E4 = E / 4;

    // 1: prolog  2: node gemm  3: count  4: conv gemm l0 (profiled slot)
    prolog_k<<<(N * 16 + 255) / 256, 256>>>(node_w, conv_w, (const float4*)x,
                                            (uint2*)pAH, (uint2*)pAL,
                                            cnt, stats, pool, ctr, N);
    gemm_tc_k<<<ggrid, 256, GSMEM>>>(pAH, pAL, BtH + NODE_OFF, BtL + NODE_OFF,
                                     node_b, nullptr, qAH, qAL, N, INdim);
    count_k<<<296, 256>>>((const int4*)coli, cnt, E4);
    gemm_tc_k<<<ggrid, 256, GSMEM>>>(qAH, qAL, BtH + CONV_OFF, BtL + CONV_OFF,
                                     nullptr, bufB, nullptr, nullptr, N, Hdim);

    // CSR build tail
    scan1_k<<<nblk1, SCAN_B>>>(cnt, partial, bsum, N);
    scan3_k<<<nblk1, SCAN_B>>>(partial, bsum, cnt, rowptr, cursor, dis, N, E, nblk1);
    fill_k<<<296, 256>>>((const int4*)rowi, (const int4*)coli, dis, cursor, csr, E4);

    // layer 0 tail (aggregate computes scale/shift for layer 0)
    aggregate_k<<<aggBlocks, 256>>>(bufB, bufA, rowptr, csr, dis, conv_b, stats,
                                    bn_g, bn_b, scale, shift, ctr, N);

    // layers 1..2
    for (int l = 1; l < NLAY; l++) {
        asplit_k<<<(N * 64 + 255) / 256, 256>>>((const float4*)bufA,
                                                scale + (l - 1) * Hdim, shift + (l - 1) * Hdim,
                                                (uint2*)pAH, (uint2*)pAL, N * 64);
        gemm_tc_k<<<ggrid, 256, GSMEM>>>(pAH, pAL,
                                         BtH + CONV_OFF + l * 65536, BtL + CONV_OFF + l * 65536,
                                         nullptr, bufB, nullptr, nullptr, N, Hdim);
        aggregate_k<<<aggBlocks, 256>>>(bufB, bufA, rowptr, csr, dis,
                                        conv_b + l * Hdim, stats + l * 2 * Hdim,
                                        bn_g + l * Hdim, bn_b + l * Hdim,
                                        scale + l * Hdim, shift + l * Hdim,
                                        ctr + l, N);
    }

    // pool (applies layer-2 BN affine + relu) + head
    pool_k<<<(N + 255) / 256, 256>>>(bufA, batch, scale + 2 * Hdim, shift + 2 * Hdim,
                                     pool, N);
    head_k<<<NGRAPH, HD2>>>(pool, head_w1, head_b1, head_w2, head_b2, out);
}

// round 15
// speedup vs baseline: 1.1998x; 1.1698x over previous
#include <cuda_runtime.h>
#include <cuda_bf16.h>
#include <cstdint>
#include <math.h>

// ---------------- problem constants ----------------
constexpr int Hdim   = 256;
constexpr int INdim  = 64;
constexpr int HD2    = 128;
constexpr int OUTdim = 12;
constexpr int NLAY   = 3;
constexpr int NGRAPH = 64;
constexpr int NMAX   = 50000;
constexpr int EMAX   = 600000;
constexpr int SCAN_B = 512;
constexpr int MAXBLK1 = (NMAX + SCAN_B - 1) / SCAN_B;

// weight scratch: bf16 split + transposed [N][K]
constexpr int COMB_OFF = 0;                      // Wc = Wn*W0 : 256 x 64
constexpr int CONV_OFF = 256 * 64;               // 3 x (256 x 256)
constexpr int WTOT     = CONV_OFF + 3 * 256 * 256;

// ---------------- scratch (device globals, no allocation) ----------------
__device__ float  g_bufA[(size_t)NMAX * Hdim];
__device__ float  g_bufB[(size_t)NMAX * Hdim];
__device__ float  g_dis[NMAX];
__device__ int    g_cnt[NMAX];
__device__ int    g_rowptr[NMAX + 1];
__device__ int    g_cursor[NMAX];
__device__ int    g_partial[NMAX];
__device__ int    g_bsum[MAXBLK1 + 1];
__device__ int2   g_csr[EMAX];
__device__ double g_stats[NLAY * 2 * Hdim];
__device__ float  g_scale[NLAY * Hdim];
__device__ float  g_shift[NLAY * Hdim];
__device__ float  g_pool[NGRAPH * Hdim];
__device__ float  g_bc[Hdim];
__device__ int    g_ctr[8];
__device__ __nv_bfloat16 g_BtH[WTOT];
__device__ __nv_bfloat16 g_BtL[WTOT];
__device__ __nv_bfloat16 g_pAH[(size_t)NMAX * Hdim];
__device__ __nv_bfloat16 g_pAL[(size_t)NMAX * Hdim];

// ---------------- helpers ----------------
__device__ __forceinline__ uint32_t packbf2(float hi, float lo) {
    uint32_t d;
    asm("cvt.rn.bf16x2.f32 %0, %1, %2;" : "=r"(d) : "f"(hi), "f"(lo));
    return d;
}

__device__ __forceinline__ void split2(float x0, float x1, uint32_t& h, uint32_t& l) {
    h = packbf2(x1, x0);
    float f0 = __uint_as_float(h << 16);
    float f1 = __uint_as_float(h & 0xFFFF0000u);
    l = packbf2(x1 - f1, x0 - f0);
}

#define MMA_BF16(d, a, b)                                                       \
    asm volatile("mma.sync.aligned.m16n8k16.row.col.f32.bf16.bf16.f32 "        \
                 "{%0,%1,%2,%3},{%4,%5,%6,%7},{%8,%9},{%0,%1,%2,%3};"          \
                 : "+f"(d[0]), "+f"(d[1]), "+f"(d[2]), "+f"(d[3])              \
                 : "r"(a[0]), "r"(a[1]), "r"(a[2]), "r"(a[3]),                 \
                   "r"(b[0]), "r"(b[1]))

__device__ __forceinline__ void ldsm_x4(uint32_t& r0, uint32_t& r1,
                                        uint32_t& r2, uint32_t& r3, uint32_t addr) {
    asm volatile("ldmatrix.sync.aligned.m8n8.x4.shared.b16 {%0,%1,%2,%3}, [%4];"
                 : "=r"(r0), "=r"(r1), "=r"(r2), "=r"(r3) : "r"(addr));
}

__device__ __forceinline__ void cp16(uint32_t dst, const void* src, uint32_t sz) {
    asm volatile("cp.async.cg.shared.global [%0], [%1], 16, %2;"
                 :: "r"(dst), "l"(src), "r"(sz) : "memory");
}
#define CP_COMMIT() asm volatile("cp.async.commit_group;" ::: "memory")

// ---------------- prolog: zero + conv weight split + x split ------------------
__global__ void prolog_k(const float* __restrict__ conv_w,
                         const float4* __restrict__ x,
                         uint2* __restrict__ xH, uint2* __restrict__ xL,
                         int* __restrict__ cnt, double* __restrict__ stats,
                         float* __restrict__ pool, int* __restrict__ ctr, int N)
{
    int i = blockIdx.x * blockDim.x + threadIdx.x;
    if (i < N * 16) {
        float4 v = x[i];
        uint32_t h0, l0, h1, l1;
        split2(v.x, v.y, h0, l0);
        split2(v.z, v.w, h1, l1);
        xH[i] = make_uint2(h0, h1);
        xL[i] = make_uint2(l0, l1);
    }
    if (i >= CONV_OFF && i < WTOT) {
        int rel = i - CONV_OFF;
        int l = rel >> 16;
        int r2 = rel & 65535;
        int n = r2 >> 8, k = r2 & 255;
        float v = conv_w[l * 65536 + k * Hdim + n];
        __nv_bfloat16 h = __float2bfloat16(v);
        g_BtH[i] = h;
        g_BtL[i] = __float2bfloat16(v - __bfloat162float(h));
    }
    if (i < N) cnt[i] = 0;
    if (i < NLAY * 2 * Hdim) stats[i] = 0.0;
    if (i < NGRAPH * Hdim) pool[i] = 0.0f;
    if (i < 8) ctr[i] = 0;
}

// ---------------- combined weight: Wc = Wn @ W0, bc = bn @ W0 -----------------
__global__ void wc_k(const float* __restrict__ node_w, const float* __restrict__ conv_w,
                     const float* __restrict__ node_b, float* __restrict__ bc)
{
    int i = blockIdx.x * blockDim.x + threadIdx.x;
    if (i < INdim * Hdim) {
        int a = i >> 8, nn = i & 255;
        float s = 0.f;
#pragma unroll 8
        for (int m = 0; m < Hdim; m++)
            s = fmaf(node_w[a * Hdim + m], conv_w[m * Hdim + nn], s);
        __nv_bfloat16 h = __float2bfloat16(s);
        g_BtH[COMB_OFF + nn * INdim + a] = h;
        g_BtL[COMB_OFF + nn * INdim + a] = __float2bfloat16(s - __bfloat162float(h));
    } else if (i < INdim * Hdim + Hdim) {
        int nn = i - INdim * Hdim;
        float s = 0.f;
        for (int m = 0; m < Hdim; m++)
            s = fmaf(node_b[m], conv_w[m * Hdim + nn], s);
        bc[nn] = s;
    }
}

// ---------------- activation split (+ BN affine + relu) ----------------------
__global__ void asplit_k(const float4* __restrict__ src,
                         const float* __restrict__ scale, const float* __restrict__ shift,
                         uint2* __restrict__ dH, uint2* __restrict__ dL, int n4)
{
    int i = blockIdx.x * blockDim.x + threadIdx.x;
    if (i >= n4) return;
    float4 v = src[i];
    int f = (i & 63) * 4;
    float4 sc = *(const float4*)(scale + f);
    float4 sh = *(const float4*)(shift + f);
    v.x = fmaxf(fmaf(v.x, sc.x, sh.x), 0.f);
    v.y = fmaxf(fmaf(v.y, sc.y, sh.y), 0.f);
    v.z = fmaxf(fmaf(v.z, sc.z, sh.z), 0.f);
    v.w = fmaxf(fmaf(v.w, sc.w, sh.w), 0.f);
    uint32_t h0, l0, h1, l1;
    split2(v.x, v.y, h0, l0);
    split2(v.z, v.w, h1, l1);
    dH[i] = make_uint2(h0, h1);
    dL[i] = make_uint2(l0, l1);
}

// ---------------- CSR build (int4-vectorized) ----------------
__global__ void count_k(const int4* __restrict__ coli4, int* __restrict__ cnt, int E4) {
    int i = blockIdx.x * blockDim.x + threadIdx.x;
    int stride = gridDim.x * blockDim.x;
    for (int e = i; e < E4; e += stride) {
        int4 c = coli4[e];
        atomicAdd(&cnt[c.x], 1);
        atomicAdd(&cnt[c.y], 1);
        atomicAdd(&cnt[c.z], 1);
        atomicAdd(&cnt[c.w], 1);
    }
}

__global__ void scan1_k(const int* __restrict__ cnt, int* __restrict__ partial,
                        int* __restrict__ bsum, int N)
{
    __shared__ int sh[SCAN_B];
    int t = threadIdx.x;
    int i = blockIdx.x * SCAN_B + t;
    int v = (i < N) ? cnt[i] : 0;
    sh[t] = v;
    __syncthreads();
#pragma unroll
    for (int off = 1; off < SCAN_B; off <<= 1) {
        int add = (t >= off) ? sh[t - off] : 0;
        __syncthreads();
        sh[t] += add;
        __syncthreads();
    }
    if (i < N) partial[i] = sh[t] - v;
    if (t == SCAN_B - 1) bsum[blockIdx.x] = sh[t];
}

__global__ void scan3_k(const int* __restrict__ partial, const int* __restrict__ bsum,
                        const int* __restrict__ cnt, int* __restrict__ rowptr,
                        int* __restrict__ cursor, float* __restrict__ dis,
                        int N, int E, int nb)
{
    __shared__ int sh[SCAN_B];
    __shared__ int ex[SCAN_B];
    int t = threadIdx.x;
    int v = (t < nb) ? bsum[t] : 0;
    sh[t] = v;
    __syncthreads();
#pragma unroll
    for (int off = 1; off < SCAN_B; off <<= 1) {
        int add = (t >= off) ? sh[t - off] : 0;
        __syncthreads();
        sh[t] += add;
        __syncthreads();
    }
    ex[t] = sh[t] - v;
    __syncthreads();
    int i = blockIdx.x * SCAN_B + t;
    if (i < N) {
        int rp = partial[i] + ex[i / SCAN_B];
        rowptr[i] = rp;
        cursor[i] = rp;
        dis[i] = rsqrtf((float)(cnt[i] + 1));
    }
    if (i == 0) rowptr[N] = E;
}

__global__ void fill_k(const int4* __restrict__ rowi4, const int4* __restrict__ coli4,
                       const float* __restrict__ dis, int* __restrict__ cursor,
                       int2* __restrict__ csr, int E4)
{
    int i = blockIdx.x * blockDim.x + threadIdx.x;
    int stride = gridDim.x * blockDim.x;
    for (int e = i; e < E4; e += stride) {
        int4 r4 = rowi4[e];
        int4 c4 = coli4[e];
        int slot;
        slot = atomicAdd(&cursor[c4.x], 1);
        csr[slot] = make_int2(r4.x, __float_as_int(dis[r4.x] * dis[c4.x]));
        slot = atomicAdd(&cursor[c4.y], 1);
        csr[slot] = make_int2(r4.y, __float_as_int(dis[r4.y] * dis[c4.y]));
        slot = atomicAdd(&cursor[c4.z], 1);
        csr[slot] = make_int2(r4.z, __float_as_int(dis[r4.z] * dis[c4.z]));
        slot = atomicAdd(&cursor[c4.w], 1);
        csr[slot] = make_int2(r4.w, __float_as_int(dis[r4.w] * dis[c4.w]));
    }
}

// ---------------- tensor-core GEMM (pre-split bf16, cp.async 4-stage) ---------
// Block tile 128x128, 8 warps (4m x 2n), warp tile 32x64 (2 n-batches of 32).
constexpr int GBM = 128, GBN = 128, GBK = 16;
constexpr int PADW = 12;
constexpr uint32_t OFF_AH = 0;
constexpr uint32_t OFF_AL = 6144;
constexpr uint32_t OFF_BH = 12288;
constexpr uint32_t OFF_BL = 18432;
constexpr uint32_t STAGE  = 24576;
constexpr int NSTAGE = 4;
constexpr int GSMEM = STAGE * NSTAGE;          // 98304

__global__ __launch_bounds__(256, 2)
void gemm_tc_k(const __nv_bfloat16* __restrict__ AH, const __nv_bfloat16* __restrict__ AL,
               const __nv_bfloat16* __restrict__ BtH, const __nv_bfloat16* __restrict__ BtL,
               const float* __restrict__ bias, float* __restrict__ C,
               int M, int K)
{
    extern __shared__ __align__(16) uint8_t dsm[];
    uint32_t sb = (uint32_t)__cvta_generic_to_shared(dsm);

    int tid = threadIdx.x;
    int wid = tid >> 5, lane = tid & 31;
    int g = lane >> 2, t4 = lane & 3;
    int wm = wid & 3, wn = wid >> 2;

    int rowBase = blockIdx.y * GBM;
    int colBase = blockIdx.x * GBN;

    float acc[2][8][4];
#pragma unroll
    for (int m = 0; m < 2; m++)
#pragma unroll
        for (int na = 0; na < 8; na++)
#pragma unroll
            for (int c = 0; c < 4; c++) acc[m][na][c] = 0.0f;

    int arow = tid >> 1, ahalf = tid & 1;
    uint32_t asz = ((rowBase + arow) < M) ? 16u : 0u;
    const __nv_bfloat16* aphSrc = AH + (size_t)(rowBase + arow) * K + ahalf * 8;
    const __nv_bfloat16* aplSrc = AL + (size_t)(rowBase + arow) * K + ahalf * 8;
    uint32_t aDst = sb + arow * 48 + ahalf * 16;
    int bn = tid >> 1, bhalf = tid & 1;
    const __nv_bfloat16* bphSrc = BtH + (size_t)(colBase + bn) * K + bhalf * 8;
    const __nv_bfloat16* bplSrc = BtL + (size_t)(colBase + bn) * K + bhalf * 8;
    uint32_t bDst = sb + bn * 48 + bhalf * 16;

    int lr = lane & 7;
    int sel = lane >> 3;
    int aRowF  = wm * 32 + (sel & 1) * 8 + lr;
    int aWordF = (sel >> 1) * 4;
    int bRowF  = wn * 64 + (sel >> 1) * 8 + lr;
    int bWordF = (sel & 1) * 4;
    uint32_t aFH = sb + OFF_AH + (aRowF * PADW + aWordF) * 4;
    uint32_t aFL = sb + OFF_AL + (aRowF * PADW + aWordF) * 4;
    uint32_t bFH = sb + OFF_BH + (bRowF * PADW + bWordF) * 4;
    uint32_t bFL = sb + OFF_BL + (bRowF * PADW + bWordF) * 4;
    constexpr uint32_t A_MSTEP = 16 * 48;
    constexpr uint32_t B_PSTEP = 16 * 48;

    auto issue = [&](int t) {
        uint32_t so = (uint32_t)(t % NSTAGE) * STAGE;
        int k0 = t * GBK;
        cp16(aDst + so + OFF_AH, aphSrc + k0, asz);
        cp16(aDst + so + OFF_AL, aplSrc + k0, asz);
        cp16(bDst + so + OFF_BH, bphSrc + k0, 16u);
        cp16(bDst + so + OFF_BL, bplSrc + k0, 16u);
        CP_COMMIT();
    };

    int nT = K / GBK;
    issue(0);
    if (nT > 1) issue(1);
    if (nT > 2) issue(2);

    for (int t = 0; t < nT; t++) {
        int inflight = (nT - 1 - t < 2) ? (nT - 1 - t) : 2;
        if (inflight == 2)      asm volatile("cp.async.wait_group 2;" ::: "memory");
        else if (inflight == 1) asm volatile("cp.async.wait_group 1;" ::: "memory");
        else                    asm volatile("cp.async.wait_group 0;" ::: "memory");
        __syncthreads();
        if (t + 3 < nT) issue(t + 3);

        uint32_t so = (uint32_t)(t % NSTAGE) * STAGE;
        uint32_t aH[2][4], aL[2][4];
#pragma unroll
        for (int m = 0; m < 2; m++) {
            ldsm_x4(aH[m][0], aH[m][1], aH[m][2], aH[m][3], aFH + so + m * A_MSTEP);
            ldsm_x4(aL[m][0], aL[m][1], aL[m][2], aL[m][3], aFL + so + m * A_MSTEP);
        }
#pragma unroll
        for (int bb = 0; bb < 2; bb++) {
            uint32_t bHf[4][2], bLf[4][2];
#pragma unroll
            for (int p2 = 0; p2 < 2; p2++) {
                int p = bb * 2 + p2;
                ldsm_x4(bHf[2 * p2][0], bHf[2 * p2][1], bHf[2 * p2 + 1][0], bHf[2 * p2 + 1][1],
                        bFH + so + p * B_PSTEP);
                ldsm_x4(bLf[2 * p2][0], bLf[2 * p2][1], bLf[2 * p2 + 1][0], bLf[2 * p2 + 1][1],
                        bFL + so + p * B_PSTEP);
            }
#pragma unroll
            for (int m = 0; m < 2; m++)
#pragma unroll
                for (int nn = 0; nn < 4; nn++) MMA_BF16(acc[m][bb * 4 + nn], aH[m], bHf[nn]);
#pragma unroll
            for (int m = 0; m < 2; m++)
#pragma unroll
                for (int nn = 0; nn < 4; nn++) MMA_BF16(acc[m][bb * 4 + nn], aH[m], bLf[nn]);
#pragma unroll
            for (int m = 0; m < 2; m++)
#pragma unroll
                for (int nn = 0; nn < 4; nn++) MMA_BF16(acc[m][bb * 4 + nn], aL[m], bHf[nn]);
        }
    }

    // epilogue (fp32 out + bias)
#pragma unroll
    for (int m = 0; m < 2; m++) {
        int r0 = rowBase + wm * 32 + m * 16 + g;
#pragma unroll
        for (int na = 0; na < 8; na++) {
            int col = colBase + wn * 64 + na * 8 + 2 * t4;
            float b0 = 0.f, b1 = 0.f;
            if (bias) { b0 = bias[col]; b1 = bias[col + 1]; }
            if (r0 < M)
                *(float2*)&C[(size_t)r0 * Hdim + col] =
                    make_float2(acc[m][na][0] + b0, acc[m][na][1] + b1);
            if (r0 + 8 < M)
                *(float2*)&C[(size_t)(r0 + 8) * Hdim + col] =
                    make_float2(acc[m][na][2] + b0, acc[m][na][3] + b1);
        }
    }
}

// ---------------- aggregate + fused BN stats + fused bn_final -----------------
__device__ __forceinline__ void fma4(float4& a, const float4& v, float s) {
    a.x = fmaf(v.x, s, a.x); a.y = fmaf(v.y, s, a.y);
    a.z = fmaf(v.z, s, a.z); a.w = fmaf(v.w, s, a.w);
}

__global__ __launch_bounds__(256)
void aggregate_k(const float* __restrict__ hw, float* __restrict__ agg,
                 const int* __restrict__ rowptr, const int2* __restrict__ csr,
                 const float* __restrict__ dis,
                 const float* __restrict__ convb, double* __restrict__ stats,
                 const float* __restrict__ gamma, const float* __restrict__ beta,
                 float* __restrict__ scaleO, float* __restrict__ shiftO,
                 int* __restrict__ ctr, int N)
{
    __shared__ float4 sh_s[8][32];
    __shared__ float4 sh_q[8][32];
    __shared__ int lastFlag;

    int tid = threadIdx.x;
    int wid = tid >> 5;
    int lane = tid & 31;

    int gw = blockIdx.x * 8 + wid;
    int half = gw & 1;
    int rowOff = half * 32 + lane;

    float4 bseg = ((const float4*)convb)[rowOff];
    float4 tsum = make_float4(0, 0, 0, 0);
    float4 tsq  = make_float4(0, 0, 0, 0);

    int nodeStride = gridDim.x * 4;

    for (int n = gw >> 1; n < N; n += nodeStride) {
        float dn = __ldg(dis + n);
        float sn = dn * dn;
        float4 acc = bseg;
        fma4(acc, ((const float4*)(hw + (size_t)n * Hdim))[rowOff], sn);

        int j  = __ldg(rowptr + n);
        int e1 = __ldg(rowptr + n + 1);

        for (; j + 3 < e1; j += 4) {
            int2 p0 = __ldg(csr + j);
            int2 p1 = __ldg(csr + j + 1);
            int2 p2 = __ldg(csr + j + 2);
            int2 p3 = __ldg(csr + j + 3);
            float4 v0 = ((const float4*)(hw + (size_t)p0.x * Hdim))[rowOff];
            float4 v1 = ((const float4*)(hw + (size_t)p1.x * Hdim))[rowOff];
            float4 v2 = ((const float4*)(hw + (size_t)p2.x * Hdim))[rowOff];
            float4 v3 = ((const float4*)(hw + (size_t)p3.x * Hdim))[rowOff];
            fma4(acc, v0, __int_as_float(p0.y));
            fma4(acc, v1, __int_as_float(p1.y));
            fma4(acc, v2, __int_as_float(p2.y));
            fma4(acc, v3, __int_as_float(p3.y));
        }
        for (; j < e1; j++) {
            int2 p = __ldg(csr + j);
            float4 v = ((const float4*)(hw + (size_t)p.x * Hdim))[rowOff];
            fma4(acc, v, __int_as_float(p.y));
        }

        ((float4*)(agg + (size_t)n * Hdim))[rowOff] = acc;

        tsum.x += acc.x; tsum.y += acc.y; tsum.z += acc.z; tsum.w += acc.w;
        tsq.x = fmaf(acc.x, acc.x, tsq.x); tsq.y = fmaf(acc.y, acc.y, tsq.y);
        tsq.z = fmaf(acc.z, acc.z, tsq.z); tsq.w = fmaf(acc.w, acc.w, tsq.w);
    }

    sh_s[wid][lane] = tsum;
    sh_q[wid][lane] = tsq;
    __syncthreads();

    int f = tid;
    int f4 = f >> 2, comp = f & 3;
    int hf = f4 >> 5, l = f4 & 31;
    float s = 0.f, q = 0.f;
#pragma unroll
    for (int k = 0; k < 4; k++) {
        int w = hf + 2 * k;
        s += ((const float*)&sh_s[w][l])[comp];
        q += ((const float*)&sh_q[w][l])[comp];
    }
    atomicAdd(&stats[f], (double)s);
    atomicAdd(&stats[Hdim + f], (double)q);

    __threadfence();
    __syncthreads();
    if (tid == 0) lastFlag = (atomicAdd(ctr, 1) == (int)gridDim.x - 1);
    __syncthreads();
    if (lastFlag) {
        double sm = __ldcg(&stats[f]);
        double sq = __ldcg(&stats[Hdim + f]);
        double mean = sm / N;
        double var = sq / N - mean * mean;
        float sc = gamma[f] * rsqrtf((float)var + 1e-5f);
        scaleO[f] = sc;
        shiftO[f] = beta[f] - (float)mean * sc;
    }
}

// ---------------- global add pool with fused BN affine + ReLU ----------------
__global__ void pool_k(const float* __restrict__ h, const int* __restrict__ batch,
                       const float* __restrict__ scale, const float* __restrict__ shift,
                       float* __restrict__ g, int N)
{
    constexpr int CH = 256;
    int f = threadIdx.x;
    int r0 = blockIdx.x * CH;
    int r1 = min(N, r0 + CH);
    if (r0 >= N) return;
    float sc = scale[f], sh = shift[f];
    int cur = batch[r0];
    float s = 0.f;
    for (int r = r0; r < r1; r++) {
        int b = batch[r];
        if (b != cur) {
            atomicAdd(&g[cur * Hdim + f], s);
            s = 0.f;
            cur = b;
        }
        s += fmaxf(fmaf(h[(size_t)r * Hdim + f], sc, sh), 0.f);
    }
    atomicAdd(&g[cur * Hdim + f], s);
}

// ---------------- MLP head ----------------
__global__ void head_k(const float* __restrict__ g, const float* __restrict__ w1,
                       const float* __restrict__ b1, const float* __restrict__ w2,
                       const float* __restrict__ b2, float* __restrict__ out)
{
    __shared__ float gs[Hdim];
    __shared__ float zs[HD2];
    int b = blockIdx.x;
    int t = threadIdx.x;
    gs[t]       = g[b * Hdim + t];
    gs[t + 128] = g[b * Hdim + t + 128];
    __syncthreads();
    float acc = b1[t];
    for (int k = 0; k < Hdim; k++) acc = fmaf(gs[k], w1[k * HD2 + t], acc);
    zs[t] = fmaxf(acc, 0.f);
    __syncthreads();
    if (t < OUTdim) {
        float o = b2[t];
        for (int k = 0; k < HD2; k++) o = fmaf(zs[k], w2[k * OUTdim + t], o);
        out[b * OUTdim + t] = o;
    }
}

// ---------------- launch ----------------
extern "C" void kernel_launch(void* const* d_in, const int* in_sizes, int n_in,
                              void* d_out, int out_size)
{
    const float* x       = (const float*)d_in[0];
    const int*   ei      = (const int*)d_in[1];
    const int*   batch   = (const int*)d_in[2];
    const float* node_w  = (const float*)d_in[3];
    const float* node_b  = (const float*)d_in[4];
    const float* conv_w  = (const float*)d_in[5];
    const float* conv_b  = (const float*)d_in[6];
    const float* bn_g    = (const float*)d_in[7];
    const float* bn_b    = (const float*)d_in[8];
    const float* head_w1 = (const float*)d_in[9];
    const float* head_b1 = (const float*)d_in[10];
    const float* head_w2 = (const float*)d_in[11];
    const float* head_b2 = (const float*)d_in[12];
    float* out = (float*)d_out;

    int N = in_sizes[0] / INdim;
    int E = in_sizes[1] / 2;
    const int* rowi = ei;
    const int* coli = ei + E;

    float *bufA, *bufB, *dis, *scale, *shift, *pool, *bc;
    int *cnt, *rowptr, *cursor, *partial, *bsum, *ctr;
    int2* csr;
    double* stats;
    __nv_bfloat16 *BtH, *BtL, *pAH, *pAL;
    cudaGetSymbolAddress((void**)&bufA, g_bufA);
    cudaGetSymbolAddress((void**)&bufB, g_bufB);
    cudaGetSymbolAddress((void**)&dis, g_dis);
    cudaGetSymbolAddress((void**)&cnt, g_cnt);
    cudaGetSymbolAddress((void**)&rowptr, g_rowptr);
    cudaGetSymbolAddress((void**)&cursor, g_cursor);
    cudaGetSymbolAddress((void**)&partial, g_partial);
    cudaGetSymbolAddress((void**)&bsum, g_bsum);
    cudaGetSymbolAddress((void**)&csr, g_csr);
    cudaGetSymbolAddress((void**)&stats, g_stats);
    cudaGetSymbolAddress((void**)&scale, g_scale);
    cudaGetSymbolAddress((void**)&shift, g_shift);
    cudaGetSymbolAddress((void**)&pool, g_pool);
    cudaGetSymbolAddress((void**)&bc, g_bc);
    cudaGetSymbolAddress((void**)&ctr, g_ctr);
    cudaGetSymbolAddress((void**)&BtH, g_BtH);
    cudaGetSymbolAddress((void**)&BtL, g_BtL);
    cudaGetSymbolAddress((void**)&pAH, g_pAH);
    cudaGetSymbolAddress((void**)&pAL, g_pAL);

    static int initDone = 0;
    static cudaStream_t s2;
    static cudaEvent_t evFork, evJoin;
    if (!initDone) {
        cudaFuncSetAttribute(gemm_tc_k, cudaFuncAttributeMaxDynamicSharedMemorySize, GSMEM);
        cudaStreamCreateWithFlags(&s2, cudaStreamNonBlocking);
        cudaEventCreateWithFlags(&evFork, cudaEventDisableTiming);
        cudaEventCreateWithFlags(&evJoin, cudaEventDisableTiming);
        initDone = 1;
    }

    int nblk1 = (N + SCAN_B - 1) / SCAN_B;
    dim3 ggrid(Hdim / GBN, (N + GBM - 1) / GBM);   // (2, 391)
    int aggBlocks = 592;
    int E4 = E / 4;

    // main: prolog + combined weight
    prolog_k<<<(N * 16 + 255) / 256, 256>>>(conv_w, (const float4*)x,
                                            (uint2*)pAH, (uint2*)pAL,
                                            cnt, stats, pool, ctr, N);
    wc_k<<<(INdim * Hdim + Hdim + 255) / 256, 256>>>(node_w, conv_w, node_b, bc);

    // fork: CSR build on s2 (depends only on prolog's cnt zeroing)
    cudaEventRecord(evFork, 0);
    cudaStreamWaitEvent(s2, evFork, 0);
    count_k<<<296, 256, 0, s2>>>((const int4*)coli, cnt, E4);
    scan1_k<<<nblk1, SCAN_B, 0, s2>>>(cnt, partial, bsum, N);
    scan3_k<<<nblk1, SCAN_B, 0, s2>>>(partial, bsum, cnt, rowptr, cursor, dis, N, E, nblk1);
    fill_k<<<296, 256, 0, s2>>>((const int4*)rowi, (const int4*)coli, dis, cursor, csr, E4);
    cudaEventRecord(evJoin, s2);

    // main: layer-0 combined GEMM  hw0 = x @ Wc + bc   (K = 64)
    gemm_tc_k<<<ggrid, 256, GSMEM>>>(pAH, pAL, BtH + COMB_OFF, BtL + COMB_OFF,
                                     bc, bufB, N, INdim);

    // join: aggregate needs CSR + hw0
    cudaStreamWaitEvent(0, evJoin, 0);
    aggregate_k<<<aggBlocks, 256>>>(bufB, bufA, rowptr, csr, dis, conv_b, stats,
                                    bn_g, bn_b, scale, shift, ctr, N);

    // layers 1..2
    for (int l = 1; l < NLAY; l++) {
        asplit_k<<<(N * 64 + 255) / 256, 256>>>((const float4*)bufA,
                                                scale + (l - 1) * Hdim, shift + (l - 1) * Hdim,
                                                (uint2*)pAH, (uint2*)pAL, N * 64);
        gemm_tc_k<<<ggrid, 256, GSMEM>>>(pAH, pAL,
                                         BtH + CONV_OFF + l * 65536, BtL + CONV_OFF + l * 65536,
                                         nullptr, bufB, N, Hdim);
        aggregate_k<<<aggBlocks, 256>>>(bufB, bufA, rowptr, csr, dis,
                                        conv_b + l * Hdim, stats + l * 2 * Hdim,
                                        bn_g + l * Hdim, bn_b + l * Hdim,
                                        scale + l * Hdim, shift + l * Hdim,
                                        ctr + l, N);
    }

    // pool (applies layer-2 BN affine + relu) + head
    pool_k<<<(N + 255) / 256, 256>>>(bufA, batch, scale + 2 * Hdim, shift + 2 * Hdim,
                                     pool, N);
    head_k<<<NGRAPH, HD2>>>(pool, head_w1, head_b1, head_w2, head_b2, out);
}